// round 11
// baseline (speedup 1.0000x reference)
#include <cuda_runtime.h>
#include <math.h>
#include <stdint.h>

// ---------------------------------------------------------------------------
// Problem constants (fixed shapes)
// ---------------------------------------------------------------------------
constexpr int Bc   = 2;
constexpr int Sc   = 2048;
constexpr int Hc   = 2048;
constexpr int KVHc = 8;
constexpr int QPKc = 4;
constexpr int Dc   = 64;
constexpr int KVc  = 512;    // KVH * D
constexpr int FFc  = 8192;
constexpr int MR   = Bc * Sc;            // 4096 rows
constexpr int NHEADZ = Bc * KVHc * QPKc; // 64 head instances

// ---------------------------------------------------------------------------
// Scratch (device globals; no runtime allocation allowed)
// ---------------------------------------------------------------------------
__device__ float g_h  [(size_t)MR * Hc];
__device__ float g_q  [(size_t)MR * Hc];
__device__ float g_k  [(size_t)MR * KVc];
__device__ float g_v  [(size_t)MR * KVc];
__device__ float g_o  [(size_t)MR * Hc];
__device__ float g_x1 [(size_t)MR * Hc];
__device__ float g_h2 [(size_t)MR * Hc];
__device__ float g_m1 [(size_t)MR * FFc];

// ---------------------------------------------------------------------------
// Helpers
// ---------------------------------------------------------------------------
__device__ __forceinline__ uint32_t f2tf32(float f) {
    uint32_t u;
    asm("cvt.rna.tf32.f32 %0, %1;" : "=r"(u) : "f"(f));
    return u;
}

__device__ __forceinline__ void mma_tf32(float* c, const uint32_t* a, const uint32_t* b) {
    asm volatile(
        "mma.sync.aligned.m16n8k8.row.col.f32.tf32.tf32.f32 "
        "{%0,%1,%2,%3}, {%4,%5,%6,%7}, {%8,%9}, {%0,%1,%2,%3};\n"
        : "+f"(c[0]), "+f"(c[1]), "+f"(c[2]), "+f"(c[3])
        : "r"(a[0]), "r"(a[1]), "r"(a[2]), "r"(a[3]),
          "r"(b[0]), "r"(b[1]));
}

// FFMA-only exp; x <= 0 expected. rel err ~3e-6.
__device__ __forceinline__ float fast_exp(float x) {
    float y = x * 1.4426950408889634f;
    y = fmaxf(y, -126.0f);
    float z = y + 12582912.0f;
    int   n = __float_as_int(z) - 0x4B400000;
    float f = y - (z - 12582912.0f);
    float p =             1.3333558146428443e-3f;
    p = fmaf(p, f,        9.6181291076284772e-3f);
    p = fmaf(p, f,        5.5504108664821580e-2f);
    p = fmaf(p, f,        2.4022650695910072e-1f);
    p = fmaf(p, f,        6.9314718055994531e-1f);
    p = fmaf(p, f,        1.0f);
    return p * __int_as_float((n + 127) << 23);
}

__device__ __forceinline__ void cp_async16(uint32_t dst, const void* src) {
    asm volatile("cp.async.cg.shared.global [%0], [%1], 16;" :: "r"(dst), "l"(src));
}
#define CP_COMMIT()  asm volatile("cp.async.commit_group;\n" ::: "memory")
#define CP_WAIT(N)   asm volatile("cp.async.wait_group %0;\n" :: "n"(N) : "memory")

// ---------------------------------------------------------------------------
// LayerNorm
// ---------------------------------------------------------------------------
__global__ void ln_kernel(const float* __restrict__ x,
                          const float* __restrict__ g,
                          const float* __restrict__ b,
                          float* __restrict__ out)
{
    const int HD = Hc;
    const long long row = blockIdx.x;
    const float* xr = x + row * HD;
    float* outr = out + row * HD;
    const int tid = threadIdx.x;

    float4 v0 = *(const float4*)(xr + tid * 8);
    float4 v1 = *(const float4*)(xr + tid * 8 + 4);
    float s  = v0.x + v0.y + v0.z + v0.w + v1.x + v1.y + v1.z + v1.w;
    float sq = v0.x*v0.x + v0.y*v0.y + v0.z*v0.z + v0.w*v0.w
             + v1.x*v1.x + v1.y*v1.y + v1.z*v1.z + v1.w*v1.w;

    #pragma unroll
    for (int o = 16; o; o >>= 1) {
        s  += __shfl_xor_sync(0xffffffffu, s,  o);
        sq += __shfl_xor_sync(0xffffffffu, sq, o);
    }
    __shared__ float ss[8], ssq[8];
    if ((tid & 31) == 0) { ss[tid >> 5] = s; ssq[tid >> 5] = sq; }
    __syncthreads();
    float ts = 0.f, tsq = 0.f;
    #pragma unroll
    for (int i = 0; i < 8; i++) { ts += ss[i]; tsq += ssq[i]; }

    const float mu  = ts * (1.0f / HD);
    const float var = tsq * (1.0f / HD) - mu * mu;
    const float inv = rsqrtf(var + 1e-5f);

    float4 gg0 = *(const float4*)(g + tid * 8);
    float4 gg1 = *(const float4*)(g + tid * 8 + 4);
    float4 bb0 = *(const float4*)(b + tid * 8);
    float4 bb1 = *(const float4*)(b + tid * 8 + 4);

    float4 o0, o1;
    o0.x = (v0.x - mu) * inv * gg0.x + bb0.x;
    o0.y = (v0.y - mu) * inv * gg0.y + bb0.y;
    o0.z = (v0.z - mu) * inv * gg0.z + bb0.z;
    o0.w = (v0.w - mu) * inv * gg0.w + bb0.w;
    o1.x = (v1.x - mu) * inv * gg1.x + bb1.x;
    o1.y = (v1.y - mu) * inv * gg1.y + bb1.y;
    o1.z = (v1.z - mu) * inv * gg1.z + bb1.z;
    o1.w = (v1.w - mu) * inv * gg1.w + bb1.w;
    *(float4*)(outr + tid * 8)     = o0;
    *(float4*)(outr + tid * 8 + 4) = o1;
}

// ---------------------------------------------------------------------------
// tf32 GEMM v6: CTA tile 128x128 with FOUR warps (128 threads), warp tile
// 64x64 (MT=4, NT=8). Same smem-traffic ratio as v5 (0.125 B/MAC, crossbar
// balance point) but inside the PROVEN gemm4 envelope: static 2-stage smem
// (37888 B), no dynamic-smem attribute on gemm, 2 CTAs/SM.
//   A: [M,K] row-major; B: [K,N] row-major.
//   Stage: As[128][20] + Bs[16][136].
//   EPI: 1 +bias, 2 res+acc+bias, 3 gelu(acc+bias)
//   KVSEL=1: grid.x doubled; second half uses Bm2/bias2/C2 (fused K+V proj).
// ---------------------------------------------------------------------------
constexpr int G_LDA   = 20;
constexpr int G_LDB   = 136;
constexpr int G_ASZ   = 128 * G_LDA;            // 2560 floats
constexpr int G_STAGE = G_ASZ + 16 * G_LDB;     // 4736 floats (18944 B)

template<int EPI, int KVSEL>
__global__ __launch_bounds__(128, 2)
void gemm6(const float* __restrict__ A, int lda,
           const float* __restrict__ Bm, int ldb,
           float* __restrict__ C, int ldc,
           int K,
           const float* __restrict__ bias,
           const float* __restrict__ res,
           const float* __restrict__ Bm2,
           const float* __restrict__ bias2,
           float* __restrict__ C2)
{
    __shared__ float smem[2 * G_STAGE];

    const int tid  = threadIdx.x;
    const int warp = tid >> 5;
    const int lane = tid & 31;
    const int g    = lane >> 2;
    const int tg   = lane & 3;
    const int wrow = warp >> 1;   // 0..1  (M direction, 64 rows each)
    const int wcol = warp & 1;    // 0..1  (N direction, 64 cols each)

    const int cRow = blockIdx.y;
    int cCol = blockIdx.x;
    if (KVSEL) {
        const int half = gridDim.x >> 1;
        if (cCol >= half) { Bm = Bm2; bias = bias2; C = C2; cCol -= half; }
    }

    const uint32_t smem_b = (uint32_t)__cvta_generic_to_shared(smem);
    const float* Ab = A + (size_t)(cRow * 128) * lda;
    const float* Bb = Bm + cCol * 128;

    float acc[4][8][4];
    #pragma unroll
    for (int mi = 0; mi < 4; mi++)
        #pragma unroll
        for (int ni = 0; ni < 8; ni++)
            #pragma unroll
            for (int r = 0; r < 4; r++) acc[mi][ni][r] = 0.f;

    const int ntiles = K >> 4;

    // cp.async coords (128 threads):
    // A: 128 rows x 16 cols = 512 float4 -> 4/thread (row = tid, col chunks)
    // B: 16 rows x 128 cols = 512 float4 -> 4/thread
    const int brow0 = tid >> 5, bcol0 = (tid & 31) * 4;

    // ---- prologue: tile 0 into stage 0 ----
    {
        const uint32_t st = smem_b;
        #pragma unroll
        for (int c = 0; c < 4; c++) {
            cp_async16(st + (tid * G_LDA + c * 4) * 4,
                       Ab + (size_t)tid * lda + c * 4);
        }
        #pragma unroll
        for (int c = 0; c < 4; c++) {
            int k = brow0 + c * 4;
            cp_async16(st + (G_ASZ + k * G_LDB + bcol0) * 4,
                       Bb + (size_t)k * ldb + bcol0);
        }
        CP_COMMIT();
    }

    for (int kt = 0; kt < ntiles; ++kt) {
        // ---- issue tile kt+1 into the other stage, then wait for tile kt ----
        if (kt + 1 < ntiles) {
            const int k0 = (kt + 1) * 16;
            const uint32_t st = smem_b + ((kt + 1) & 1) * G_STAGE * 4;
            #pragma unroll
            for (int c = 0; c < 4; c++) {
                cp_async16(st + (tid * G_LDA + c * 4) * 4,
                           Ab + (size_t)tid * lda + k0 + c * 4);
            }
            #pragma unroll
            for (int c = 0; c < 4; c++) {
                int k = brow0 + c * 4;
                cp_async16(st + (G_ASZ + k * G_LDB + bcol0) * 4,
                           Bb + (size_t)(k0 + k) * ldb + bcol0);
            }
            CP_COMMIT();
            CP_WAIT(1);
        } else {
            CP_WAIT(0);
        }
        __syncthreads();

        const float* As = smem + (kt & 1) * G_STAGE;
        const float* Bs = As + G_ASZ;

        #pragma unroll
        for (int kk = 0; kk < 16; kk += 8) {
            uint32_t af[4][4], bf[8][2];
            #pragma unroll
            for (int mi = 0; mi < 4; mi++) {
                const int mm0 = wrow * 64 + mi * 16;
                af[mi][0] = __float_as_uint(As[(mm0 + g)     * G_LDA + kk + tg]);
                af[mi][1] = __float_as_uint(As[(mm0 + g + 8) * G_LDA + kk + tg]);
                af[mi][2] = __float_as_uint(As[(mm0 + g)     * G_LDA + kk + tg + 4]);
                af[mi][3] = __float_as_uint(As[(mm0 + g + 8) * G_LDA + kk + tg + 4]);
            }
            #pragma unroll
            for (int ni = 0; ni < 8; ni++) {
                const int n0 = wcol * 64 + ni * 8 + g;
                bf[ni][0] = __float_as_uint(Bs[(kk + tg)     * G_LDB + n0]);
                bf[ni][1] = __float_as_uint(Bs[(kk + tg + 4) * G_LDB + n0]);
            }
            #pragma unroll
            for (int mi = 0; mi < 4; mi++)
                #pragma unroll
                for (int ni = 0; ni < 8; ni++)
                    mma_tf32(acc[mi][ni], af[mi], bf[ni]);
        }
        __syncthreads();   // free stage kt&1 for iteration kt+1's issue
    }

    // ---- epilogue ----
    #pragma unroll
    for (int mi = 0; mi < 4; mi++) {
        #pragma unroll
        for (int ni = 0; ni < 8; ni++) {
            const int row0 = cRow * 128 + wrow * 64 + mi * 16 + g;
            const int col0 = cCol * 128 + wcol * 64 + ni * 8 + 2 * tg;
            float c0 = acc[mi][ni][0];
            float c1 = acc[mi][ni][1];
            float c2 = acc[mi][ni][2];
            float c3 = acc[mi][ni][3];

            if (EPI == 1) {
                const float b0 = bias[col0], b1 = bias[col0 + 1];
                c0 += b0; c1 += b1; c2 += b0; c3 += b1;
            } else if (EPI == 2) {
                const float b0 = bias[col0], b1 = bias[col0 + 1];
                c0 += b0 + res[(size_t)row0 * ldc + col0];
                c1 += b1 + res[(size_t)row0 * ldc + col0 + 1];
                c2 += b0 + res[(size_t)(row0 + 8) * ldc + col0];
                c3 += b1 + res[(size_t)(row0 + 8) * ldc + col0 + 1];
            } else if (EPI == 3) {
                const float b0 = bias[col0], b1 = bias[col0 + 1];
                c0 += b0; c1 += b1; c2 += b0; c3 += b1;
                c0 = 0.5f * c0 * (1.0f + erff(c0 * 0.70710678118654752f));
                c1 = 0.5f * c1 * (1.0f + erff(c1 * 0.70710678118654752f));
                c2 = 0.5f * c2 * (1.0f + erff(c2 * 0.70710678118654752f));
                c3 = 0.5f * c3 * (1.0f + erff(c3 * 0.70710678118654752f));
            }

            *(float2*)&C[(size_t)row0 * ldc + col0]       = make_float2(c0, c1);
            *(float2*)&C[(size_t)(row0 + 8) * ldc + col0] = make_float2(c2, c3);
        }
    }
}

// ---------------------------------------------------------------------------
// Flash attention v2 (unchanged — 667us verified in R8).
// ---------------------------------------------------------------------------
constexpr int LDQ = 68, LDK = 68, LDV = 72;
constexpr int SMF_Q   = 0;
constexpr int SMF_K0  = 128 * LDQ;
constexpr int SMF_K1  = SMF_K0 + 128 * LDK;
constexpr int SMF_V0  = SMF_K1 + 128 * LDK;
constexpr int SMF_V1  = SMF_V0 + 128 * LDV;
constexpr int SMF_MX  = SMF_V1 + 128 * LDV;
constexpr int SMF_SUM = SMF_MX + 256;
constexpr int FA_SMEM_BYTES = (SMF_SUM + 256) * 4;  // 180224

__global__ __launch_bounds__(512, 1)
void flash_kernel(const float* __restrict__ Qg, const float* __restrict__ Kg,
                  const float* __restrict__ Vg, const float* __restrict__ maskg,
                  float* __restrict__ Og)
{
    extern __shared__ float sm[];
    uint32_t* Qsu  = (uint32_t*)(sm + SMF_Q);
    float*    smx  = sm + SMF_MX;
    float*    ssum = sm + SMF_SUM;

    const int tid  = threadIdx.x;
    const int warp = tid >> 5;
    const int lane = tid & 31;
    const int g    = lane >> 2;
    const int tg   = lane & 3;
    const int r    = warp & 7;
    const int h    = warp >> 3;
    const int m0   = r * 16;
    const int qt   = blockIdx.x;
    const int z    = blockIdx.y;
    const int bi   = z >> 5, kvh = (z >> 2) & 7, qpk = z & 3;

    const float* Qh = Qg + (size_t)bi * Sc * Hc + (size_t)(qt * 128) * Hc
                    + kvh * (QPKc * Dc) + qpk * Dc;
    const float* Kh = Kg + (size_t)bi * Sc * KVc + kvh * Dc;
    const float* Vh = Vg + (size_t)bi * Sc * KVc + kvh * Dc;
    float*       Oh = Og + (size_t)bi * Sc * Hc + (size_t)(qt * 128) * Hc
                    + (kvh * QPKc + qpk) * Dc;
    const float* maskp = maskg + (size_t)bi * Sc;

    #pragma unroll
    for (int c = 0; c < 4; c++) {
        int flat = c * 512 + tid, row = flat >> 4, c4 = (flat & 15) * 4;
        float4 qv = *(const float4*)(Qh + (size_t)row * Hc + c4);
        uint32_t* d = Qsu + row * LDQ + c4;
        d[0] = f2tf32(qv.x); d[1] = f2tf32(qv.y);
        d[2] = f2tf32(qv.z); d[3] = f2tf32(qv.w);
    }

    const uint32_t k0_b = (uint32_t)__cvta_generic_to_shared(sm + SMF_K0);
    const uint32_t k1_b = (uint32_t)__cvta_generic_to_shared(sm + SMF_K1);
    const uint32_t v0_b = (uint32_t)__cvta_generic_to_shared(sm + SMF_V0);
    const uint32_t v1_b = (uint32_t)__cvta_generic_to_shared(sm + SMF_V1);

    {
        #pragma unroll
        for (int c = 0; c < 4; c++) {
            int flat = c * 512 + tid, key = flat >> 4, c4 = (flat & 15) * 4;
            cp_async16(k0_b + (key * LDK + c4) * 4, Kh + (size_t)key * KVc + c4);
        }
        CP_COMMIT();
        #pragma unroll
        for (int c = 0; c < 4; c++) {
            int flat = c * 512 + tid, key = flat >> 4, c4 = (flat & 15) * 4;
            cp_async16(v0_b + (key * LDV + c4) * 4, Vh + (size_t)key * KVc + c4);
        }
        CP_COMMIT();
    }

    float oacc[8][4];
    #pragma unroll
    for (int ni = 0; ni < 8; ni++)
        #pragma unroll
        for (int rr = 0; rr < 4; rr++) oacc[ni][rr] = 0.f;
    float m_lo = -1e30f, m_hi = -1e30f, l_lo = 0.f, l_hi = 0.f;

    for (int t = 0; t < 16; t++) {
        if (t + 1 < 16) {
            const uint32_t kb = ((t + 1) & 1) ? k1_b : k0_b;
            const uint32_t vb = ((t + 1) & 1) ? v1_b : v0_b;
            const float* Kn = Kh + (size_t)(t + 1) * 128 * KVc;
            const float* Vn = Vh + (size_t)(t + 1) * 128 * KVc;
            #pragma unroll
            for (int c = 0; c < 4; c++) {
                int flat = c * 512 + tid, key = flat >> 4, c4 = (flat & 15) * 4;
                cp_async16(kb + (key * LDK + c4) * 4, Kn + (size_t)key * KVc + c4);
            }
            CP_COMMIT();
            #pragma unroll
            for (int c = 0; c < 4; c++) {
                int flat = c * 512 + tid, key = flat >> 4, c4 = (flat & 15) * 4;
                cp_async16(vb + (key * LDV + c4) * 4, Vn + (size_t)key * KVc + c4);
            }
            CP_COMMIT();
            CP_WAIT(2);
        } else {
            CP_WAIT(0);
        }
        __syncthreads();

        const float* Ks = sm + ((t & 1) ? SMF_K1 : SMF_K0);
        const float* Vs = sm + ((t & 1) ? SMF_V1 : SMF_V0);

        float sacc[8][4];
        #pragma unroll
        for (int ni = 0; ni < 8; ni++)
            #pragma unroll
            for (int rr = 0; rr < 4; rr++) sacc[ni][rr] = 0.f;

        #pragma unroll
        for (int kk = 0; kk < 8; kk++) {
            uint32_t af[4];
            af[0] = Qsu[(m0 + g)     * LDQ + kk * 8 + tg];
            af[1] = Qsu[(m0 + g + 8) * LDQ + kk * 8 + tg];
            af[2] = Qsu[(m0 + g)     * LDQ + kk * 8 + tg + 4];
            af[3] = Qsu[(m0 + g + 8) * LDQ + kk * 8 + tg + 4];
            #pragma unroll
            for (int ni = 0; ni < 8; ni++) {
                const int key0 = h * 64 + ni * 8 + g;
                uint32_t bf[2];
                bf[0] = __float_as_uint(Ks[key0 * LDK + kk * 8 + tg]);
                bf[1] = __float_as_uint(Ks[key0 * LDK + kk * 8 + tg + 4]);
                mma_tf32(sacc[ni], af, bf);
            }
        }

        const int k0t = t * 128 + h * 64;
        float mloc_lo = -1e30f, mloc_hi = -1e30f;
        #pragma unroll
        for (int ni = 0; ni < 8; ni++) {
            float2 mk = *(const float2*)(maskp + k0t + ni * 8 + 2 * tg);
            float s0 = fmaf(sacc[ni][0], 0.125f, mk.x);
            float s1 = fmaf(sacc[ni][1], 0.125f, mk.y);
            float s2 = fmaf(sacc[ni][2], 0.125f, mk.x);
            float s3 = fmaf(sacc[ni][3], 0.125f, mk.y);
            sacc[ni][0] = s0; sacc[ni][1] = s1; sacc[ni][2] = s2; sacc[ni][3] = s3;
            mloc_lo = fmaxf(mloc_lo, fmaxf(s0, s1));
            mloc_hi = fmaxf(mloc_hi, fmaxf(s2, s3));
        }
        mloc_lo = fmaxf(mloc_lo, __shfl_xor_sync(0xffffffffu, mloc_lo, 1));
        mloc_lo = fmaxf(mloc_lo, __shfl_xor_sync(0xffffffffu, mloc_lo, 2));
        mloc_hi = fmaxf(mloc_hi, __shfl_xor_sync(0xffffffffu, mloc_hi, 1));
        mloc_hi = fmaxf(mloc_hi, __shfl_xor_sync(0xffffffffu, mloc_hi, 2));

        if (tg == 0) {
            smx[(m0 + g) * 2 + h]     = mloc_lo;
            smx[(m0 + 8 + g) * 2 + h] = mloc_hi;
        }
        __syncthreads();
        const float mo_lo = smx[(m0 + g) * 2 + (1 - h)];
        const float mo_hi = smx[(m0 + 8 + g) * 2 + (1 - h)];

        const float mnew_lo = fmaxf(m_lo, fmaxf(mloc_lo, mo_lo));
        const float mnew_hi = fmaxf(m_hi, fmaxf(mloc_hi, mo_hi));
        const float alpha_lo = fast_exp(m_lo - mnew_lo);
        const float alpha_hi = fast_exp(m_hi - mnew_hi);
        m_lo = mnew_lo; m_hi = mnew_hi;

        float rs_lo = 0.f, rs_hi = 0.f;
        #pragma unroll
        for (int ni = 0; ni < 8; ni++) {
            float p0 = fast_exp(sacc[ni][0] - mnew_lo);
            float p1 = fast_exp(sacc[ni][1] - mnew_lo);
            float p2 = fast_exp(sacc[ni][2] - mnew_hi);
            float p3 = fast_exp(sacc[ni][3] - mnew_hi);
            sacc[ni][0] = p0; sacc[ni][1] = p1; sacc[ni][2] = p2; sacc[ni][3] = p3;
            rs_lo += p0 + p1; rs_hi += p2 + p3;
        }
        rs_lo += __shfl_xor_sync(0xffffffffu, rs_lo, 1);
        rs_lo += __shfl_xor_sync(0xffffffffu, rs_lo, 2);
        rs_hi += __shfl_xor_sync(0xffffffffu, rs_hi, 1);
        rs_hi += __shfl_xor_sync(0xffffffffu, rs_hi, 2);

        if (tg == 0) {
            ssum[(m0 + g) * 2 + h]     = rs_lo;
            ssum[(m0 + 8 + g) * 2 + h] = rs_hi;
        }
        __syncthreads();
        l_lo = fmaf(l_lo, alpha_lo, rs_lo + ssum[(m0 + g) * 2 + (1 - h)]);
        l_hi = fmaf(l_hi, alpha_hi, rs_hi + ssum[(m0 + 8 + g) * 2 + (1 - h)]);

        #pragma unroll
        for (int ni = 0; ni < 8; ni++) {
            oacc[ni][0] *= alpha_lo; oacc[ni][1] *= alpha_lo;
            oacc[ni][2] *= alpha_hi; oacc[ni][3] *= alpha_hi;
        }

        const int srcA = (lane & ~3) | (tg >> 1);
        const int selb = tg & 1;
        #pragma unroll
        for (int kk = 0; kk < 8; kk++) {
            float c0 = sacc[kk][0], c1 = sacc[kk][1];
            float c2 = sacc[kk][2], c3 = sacc[kk][3];
            float s0  = __shfl_sync(0xffffffffu, c0, srcA);
            float s1  = __shfl_sync(0xffffffffu, c1, srcA);
            float s0b = __shfl_sync(0xffffffffu, c0, srcA + 2);
            float s1b = __shfl_sync(0xffffffffu, c1, srcA + 2);
            float s2  = __shfl_sync(0xffffffffu, c2, srcA);
            float s3  = __shfl_sync(0xffffffffu, c3, srcA);
            float s2b = __shfl_sync(0xffffffffu, c2, srcA + 2);
            float s3b = __shfl_sync(0xffffffffu, c3, srcA + 2);
            uint32_t af[4];
            af[0] = __float_as_uint(selb ? s1  : s0);
            af[1] = __float_as_uint(selb ? s3  : s2);
            af[2] = __float_as_uint(selb ? s1b : s0b);
            af[3] = __float_as_uint(selb ? s3b : s2b);
            const int vr0 = h * 64 + kk * 8 + tg;
            #pragma unroll
            for (int ni = 0; ni < 8; ni++) {
                uint32_t bf[2];
                bf[0] = __float_as_uint(Vs[vr0       * LDV + ni * 8 + g]);
                bf[1] = __float_as_uint(Vs[(vr0 + 4) * LDV + ni * 8 + g]);
                mma_tf32(oacc[ni], af, bf);
            }
        }
        __syncthreads();
    }

    float* smo = sm + SMF_V0;
    if (h == 1) {
        #pragma unroll
        for (int ni = 0; ni < 8; ni++) {
            *(float2*)&smo[(m0 + g)     * LDV + ni * 8 + 2 * tg] =
                make_float2(oacc[ni][0], oacc[ni][1]);
            *(float2*)&smo[(m0 + 8 + g) * LDV + ni * 8 + 2 * tg] =
                make_float2(oacc[ni][2], oacc[ni][3]);
        }
    }
    __syncthreads();
    if (h == 0) {
        const float inv_lo = 1.0f / l_lo;
        const float inv_hi = 1.0f / l_hi;
        #pragma unroll
        for (int ni = 0; ni < 8; ni++) {
            const int col = ni * 8 + 2 * tg;
            float2 a = *(float2*)&smo[(m0 + g)     * LDV + col];
            float2 b = *(float2*)&smo[(m0 + 8 + g) * LDV + col];
            *(float2*)(Oh + (size_t)(m0 + g)     * Hc + col) =
                make_float2((oacc[ni][0] + a.x) * inv_lo, (oacc[ni][1] + a.y) * inv_lo);
            *(float2*)(Oh + (size_t)(m0 + 8 + g) * Hc + col) =
                make_float2((oacc[ni][2] + b.x) * inv_hi, (oacc[ni][3] + b.y) * inv_hi);
        }
    }
}

// ---------------------------------------------------------------------------
// Launch sequence
// ---------------------------------------------------------------------------
extern "C" void kernel_launch(void* const* d_in, const int* in_sizes, int n_in,
                              void* d_out, int out_size)
{
    const float* x    = (const float*)d_in[0];
    const float* mask = (const float*)d_in[1];
    const float* Wq   = (const float*)d_in[2];
    const float* bq   = (const float*)d_in[3];
    const float* Wk   = (const float*)d_in[4];
    const float* bk   = (const float*)d_in[5];
    const float* Wv   = (const float*)d_in[6];
    const float* bv   = (const float*)d_in[7];
    const float* Wo   = (const float*)d_in[8];
    const float* bo   = (const float*)d_in[9];
    const float* W1   = (const float*)d_in[10];
    const float* b1   = (const float*)d_in[11];
    const float* W2   = (const float*)d_in[12];
    const float* b2   = (const float*)d_in[13];
    const float* g1   = (const float*)d_in[14];
    const float* be1  = (const float*)d_in[15];
    const float* g2   = (const float*)d_in[16];
    const float* be2  = (const float*)d_in[17];
    float* out = (float*)d_out;

    float *h, *q, *kq, *vq, *o, *x1, *h2, *m1;
    cudaGetSymbolAddress((void**)&h,  g_h);
    cudaGetSymbolAddress((void**)&q,  g_q);
    cudaGetSymbolAddress((void**)&kq, g_k);
    cudaGetSymbolAddress((void**)&vq, g_v);
    cudaGetSymbolAddress((void**)&o,  g_o);
    cudaGetSymbolAddress((void**)&x1, g_x1);
    cudaGetSymbolAddress((void**)&h2, g_h2);
    cudaGetSymbolAddress((void**)&m1, g_m1);

    // Only flash needs >48KB dynamic smem (this exact call passed in R3/R5/R8).
    cudaFuncSetAttribute(flash_kernel,
                         cudaFuncAttributeMaxDynamicSharedMemorySize, FA_SMEM_BYTES);

    // 1) h = LN(x)
    ln_kernel<<<MR, 256>>>(x, g1, be1, h);

    // 2) Q projection  [4096 x 2048 x 2048], grid (16, 32)
    gemm6<1, 0><<<dim3(Hc / 128, MR / 128), 128>>>(
        h, Hc, Wq, Hc, q, Hc, Hc, bq, nullptr, nullptr, nullptr, nullptr);

    // 3) K + V projections fused (grid.x = 8)
    gemm6<1, 1><<<dim3(2 * KVc / 128, MR / 128), 128>>>(
        h, Hc, Wk, KVc, kq, KVc, Hc, bk, nullptr, Wv, bv, vq);

    // 4) fused flash attention -> o
    flash_kernel<<<dim3(16, NHEADZ), 512, FA_SMEM_BYTES>>>(q, kq, vq, mask, o);

    // 5) x1 = x + o @ Wo + bo   grid (16, 32)
    gemm6<2, 0><<<dim3(Hc / 128, MR / 128), 128>>>(
        o, Hc, Wo, Hc, x1, Hc, Hc, bo, x, nullptr, nullptr, nullptr);

    // 6) h2 = LN(x1)
    ln_kernel<<<MR, 256>>>(x1, g2, be2, h2);

    // 7) m1 = gelu(h2 @ W1 + b1)   grid (64, 32)
    gemm6<3, 0><<<dim3(FFc / 128, MR / 128), 128>>>(
        h2, Hc, W1, FFc, m1, FFc, Hc, b1, nullptr, nullptr, nullptr, nullptr);

    // 8) out = x1 + m1 @ W2 + b2   grid (16, 32)
    gemm6<2, 0><<<dim3(Hc / 128, MR / 128), 128>>>(
        m1, FFc, W2, Hc, out, Hc, FFc, b2, x1, nullptr, nullptr, nullptr);
}